// round 8
// baseline (speedup 1.0000x reference)
#include <cuda_runtime.h>

#define HD 32
#define SEQ 512
#define NBW 4        // batches per warp
#define BPB 32       // batches per block
#define THREADS 256  // 8 warps

typedef unsigned long long u64;

__device__ __forceinline__ void ffma2(u64 &d, u64 a, u64 b) {
    asm("fma.rn.f32x2 %0, %1, %2, %0;" : "+l"(d) : "l"(a), "l"(b));
}
__device__ __forceinline__ u64 pack2(float lo, float hi) {
    u64 v; asm("mov.b64 %0, {%1, %2};" : "=l"(v) : "f"(lo), "f"(hi)); return v;
}
__device__ __forceinline__ float2 unpk(u64 v) {
    float2 r; asm("mov.b64 {%0, %1}, %2;" : "=f"(r.x), "=f"(r.y) : "l"(v)); return r;
}
__device__ __forceinline__ float sigm(float x) {
    return __fdividef(1.0f, 1.0f + __expf(-x));
}
__device__ __forceinline__ float tanhx(float x) {
    float xc = fminf(fmaxf(x, -15.0f), 15.0f);
    float e  = __expf(2.0f * xc);
    return __fdividef(e - 1.0f, e + 1.0f);
}

// smem layout (floats)
#define W_STRIDE 36                          // 32 + pad: conflict-free LDS.128
#define W_MAT    (128 * W_STRIDE)            // 4608
#define OFF_X    (3 * W_MAT)                 // 13824
#define X_STRIDE 33
#define OFF_H1   (OFF_X + SEQ * X_STRIDE)    // two h1 buffers
#define OFF_H2   (OFF_H1 + 2 * BPB * HD)     // two h2 buffers
#define SMEM_FLOATS (OFF_H2 + 2 * BPB * HD)

// 32xK matvec over NBW batches, K packed in pairs; accumulates onto acc.
// Full unroll (R2-style): ptxas schedules the staging; no address recompute.
__device__ __forceinline__ void matvec4(u64 (&acc)[4][NBW],
                                        const char* wbase,
                                        const float* hbuf) {
#pragma unroll
    for (int c = 0; c < 8; ++c) {            // 8 chunks of 4 k-values (16B)
        ulonglong2 wv[4];
#pragma unroll
        for (int g = 0; g < 4; ++g)
            wv[g] = *(const ulonglong2*)(wbase + g * (32 * W_STRIDE * 4) + c * 16);
#pragma unroll
        for (int b = 0; b < NBW; ++b) {
            ulonglong2 hv = *(const ulonglong2*)((const char*)hbuf + b * (HD * 4) + c * 16);
#pragma unroll
            for (int g = 0; g < 4; ++g) {
                ffma2(acc[g][b], wv[g].x, hv.x);
                ffma2(acc[g][b], wv[g].y, hv.y);
            }
        }
    }
}

extern "C" __global__ void __launch_bounds__(THREADS, 1)
lstm_kernel(const float* __restrict__ x,
            const float* __restrict__ w_ih0, const float* __restrict__ w_hh0,
            const float* __restrict__ b_ih0, const float* __restrict__ b_hh0,
            const float* __restrict__ w_ih1, const float* __restrict__ w_hh1,
            const float* __restrict__ b_ih1, const float* __restrict__ b_hh1,
            const float* __restrict__ fc1_w, const float* __restrict__ fc1_b,
            const float* __restrict__ fc2_w, const float* __restrict__ fc2_b,
            float* __restrict__ out) {
    extern __shared__ float sm[];
    float* wsm = sm;
    float* xs  = sm + OFF_X;
    float* h1buf[2] = { sm + OFF_H1, sm + OFF_H1 + BPB * HD };
    float* h2buf[2] = { sm + OFF_H2, sm + OFF_H2 + BPB * HD };

    const int tid  = threadIdx.x;
    const int bblk = blockIdx.x * BPB;

    // ---- weights into padded smem ----
    for (int i = tid; i < 3 * 128 * 32; i += THREADS) {
        int m = i >> 12;
        int r = (i >> 5) & 127;
        int k = i & 31;
        const float* src = (m == 0) ? w_hh0 : (m == 1) ? w_ih1 : w_hh1;
        wsm[m * W_MAT + r * W_STRIDE + k] = src[r * 32 + k];
    }
    // ---- x tile transposed [s][b] ----
    for (int i = tid; i < BPB * SEQ; i += THREADS) {
        int b = i >> 9;
        int s = i & (SEQ - 1);
        xs[s * X_STRIDE + b] = x[(size_t)(bblk + b) * SEQ + s];
    }
    for (int i = tid; i < BPB * HD; i += THREADS) {
        h1buf[0][i] = 0.0f; h1buf[1][i] = 0.0f;
        h2buf[0][i] = 0.0f; h2buf[1][i] = 0.0f;
    }
    __syncthreads();

    const int wid = tid >> 5;
    const int j   = tid & 31;
    const int b0  = wid * NBW;

    const char* w0base = (const char*)wsm + (size_t)j * (W_STRIDE * 4);
    const char* w1base = (const char*)(wsm + W_MAT)     + (size_t)j * (W_STRIDE * 4);
    const char* w2base = (const char*)(wsm + 2 * W_MAT) + (size_t)j * (W_STRIDE * 4);

    float wx[4], bi0[4], bi1[4];
#pragma unroll
    for (int g = 0; g < 4; ++g) {
        int r = g * 32 + j;
        wx[g]  = w_ih0[r];
        bi0[g] = b_ih0[r] + b_hh0[r];
        bi1[g] = b_ih1[r] + b_hh1[r];
    }

    float c1[NBW], c2[NBW];
#pragma unroll
    for (int b = 0; b < NBW; ++b) { c1[b] = 0.0f; c2[b] = 0.0f; }

#pragma unroll 1
    for (int s = 0; s < SEQ; ++s) {
        const int rd = (s + 1) & 1;      // previous step's buffers
        const int wr = s & 1;
        const float* h1old = h1buf[rd] + b0 * HD;
        const float* h2old = h2buf[rd] + b0 * HD;

        // ---- Layer 1: acc pre-loaded with x*wx + bias (kills zero-init + post-fmaf) ----
        u64 acc[4][NBW];
#pragma unroll
        for (int b = 0; b < NBW; ++b) {
            float xv = xs[s * X_STRIDE + b0 + b];
#pragma unroll
            for (int g = 0; g < 4; ++g)
                acc[g][b] = pack2(fmaf(xv, wx[g], bi0[g]), 0.0f);
        }
        matvec4(acc, w0base, h1old);

        float h1n[NBW];
#pragma unroll
        for (int b = 0; b < NBW; ++b) {
            float2 t;
            t = unpk(acc[0][b]); float gi = sigm (t.x + t.y);
            t = unpk(acc[1][b]); float gf = sigm (t.x + t.y);
            t = unpk(acc[2][b]); float gg = tanhx(t.x + t.y);
            t = unpk(acc[3][b]); float go = sigm (t.x + t.y);
            float cn = fmaf(gf, c1[b], gi * gg);
            c1[b] = cn;
            h1n[b] = go * tanhx(cn);
        }
#pragma unroll
        for (int b = 0; b < NBW; ++b) h1buf[wr][(b0 + b) * HD + j] = h1n[b];
        __syncwarp();                          // h1new visible to warp lanes

        // ---- Layer 2: acc reborn with bias; two matvecs back-to-back ----
#pragma unroll
        for (int b = 0; b < NBW; ++b)
#pragma unroll
            for (int g = 0; g < 4; ++g)
                acc[g][b] = pack2(bi1[g], 0.0f);

        matvec4(acc, w1base, h1buf[wr] + b0 * HD);   // L2 input proj (fresh h1)
        matvec4(acc, w2base, h2old);                 // L2 recurrent

#pragma unroll
        for (int b = 0; b < NBW; ++b) {
            float2 t;
            t = unpk(acc[0][b]); float gi = sigm (t.x + t.y);
            t = unpk(acc[1][b]); float gf = sigm (t.x + t.y);
            t = unpk(acc[2][b]); float gg = tanhx(t.x + t.y);
            t = unpk(acc[3][b]); float go = sigm (t.x + t.y);
            float cn = fmaf(gf, c2[b], gi * gg);
            c2[b] = cn;
            h2buf[wr][(b0 + b) * HD + j] = go * tanhx(cn);
        }
        __syncwarp();                          // h2new visible before next step reads it
    }

    // ================= FC head (final h2 in buf[(SEQ-1)&1]) =================
    if (j < NBW) {
        const int bl = b0 + j;
        const float* h = h2buf[(SEQ - 1) & 1] + bl * HD;
        float a1[16];
#pragma unroll
        for (int l = 0; l < 16; ++l) a1[l] = fc1_b[l];
#pragma unroll
        for (int k = 0; k < HD; ++k) {
            float hv = h[k];
#pragma unroll
            for (int l = 0; l < 16; ++l)
                a1[l] = fmaf(fc1_w[l * HD + k], hv, a1[l]);
        }
        float y = fc2_b[0];
#pragma unroll
        for (int l = 0; l < 16; ++l) {
            float a = a1[l];
            a = (a >= 0.0f) ? a : 0.2f * a;
            y = fmaf(fc2_w[l], a, y);
        }
        out[bblk + bl] = y;
    }
}

extern "C" void kernel_launch(void* const* d_in, const int* in_sizes, int n_in,
                              void* d_out, int out_size) {
    const float* x     = (const float*)d_in[0];
    const float* w_ih0 = (const float*)d_in[1];
    const float* w_hh0 = (const float*)d_in[2];
    const float* b_ih0 = (const float*)d_in[3];
    const float* b_hh0 = (const float*)d_in[4];
    const float* w_ih1 = (const float*)d_in[5];
    const float* w_hh1 = (const float*)d_in[6];
    const float* b_ih1 = (const float*)d_in[7];
    const float* b_hh1 = (const float*)d_in[8];
    const float* fc1_w = (const float*)d_in[9];
    const float* fc1_b = (const float*)d_in[10];
    const float* fc2_w = (const float*)d_in[11];
    const float* fc2_b = (const float*)d_in[12];
    float* out = (float*)d_out;

    int B = in_sizes[0] / SEQ;          // 4096
    int grid = B / BPB;                 // 128
    size_t smem = SMEM_FLOATS * sizeof(float);

    cudaFuncSetAttribute(lstm_kernel, cudaFuncAttributeMaxDynamicSharedMemorySize, (int)smem);
    lstm_kernel<<<grid, THREADS, smem>>>(x, w_ih0, w_hh0, b_ih0, b_hh0,
                                         w_ih1, w_hh1, b_ih1, b_hh1,
                                         fc1_w, fc1_b, fc2_w, fc2_b, out);
}

// round 11
// speedup vs baseline: 2.2179x; 2.2179x over previous
#include <cuda_runtime.h>

#define HD 32
#define SEQ 512
#define NBW 4        // batches per warp
#define BPB 32       // batches per block
#define THREADS 256  // 8 warps

typedef unsigned long long u64;

__device__ __forceinline__ void ffma2(u64 &d, u64 a, u64 b) {
    asm("fma.rn.f32x2 %0, %1, %2, %0;" : "+l"(d) : "l"(a), "l"(b));
}
__device__ __forceinline__ float2 unpk(u64 v) {
    float2 r; asm("mov.b64 {%0, %1}, %2;" : "=f"(r.x), "=f"(r.y) : "l"(v)); return r;
}
// Single-MUFU activations (sm_90+): tanh.approx.f32, abs err ~2^-11.
__device__ __forceinline__ float tanha(float x) {
    float y; asm("tanh.approx.f32 %0, %1;" : "=f"(y) : "f"(x)); return y;
}
__device__ __forceinline__ float sigm(float x) {
    return fmaf(tanha(0.5f * x), 0.5f, 0.5f);   // sigma(x) = (1 + tanh(x/2)) / 2
}
__device__ __forceinline__ float tanhx(float x) {
    return tanha(x);
}

// smem layout (in floats)
#define W_STRIDE 36                      // 32 + pad: conflict-free LDS.128 across lanes
#define W_MAT    (128 * W_STRIDE)        // 4608 floats per matrix
#define OFF_X    (3 * W_MAT)             // 13824
#define X_STRIDE 33                      // conflict-free transpose store
#define OFF_H1   (OFF_X + SEQ * X_STRIDE)   // 30720
#define OFF_H2   (OFF_H1 + BPB * HD)        // 31744
#define SMEM_FLOATS (OFF_H2 + BPB * HD)     // 32768 floats = 131072 B

// Accumulate one 32xK matvec (K packed in pairs) into acc[gate][batch].
__device__ __forceinline__ void matvec_acc(u64 (&acc)[4][NBW],
                                           const char* wbase,
                                           const float* hbuf) {
#pragma unroll
    for (int c = 0; c < 8; ++c) {          // 8 chunks of 4 k-values
        ulonglong2 wv[4];
#pragma unroll
        for (int g = 0; g < 4; ++g)
            wv[g] = *(const ulonglong2*)(wbase + g * (32 * W_STRIDE * 4) + c * 16);
#pragma unroll
        for (int b = 0; b < NBW; ++b) {
            ulonglong2 hv = *(const ulonglong2*)((const char*)hbuf + b * (HD * 4) + c * 16);
#pragma unroll
            for (int g = 0; g < 4; ++g) {
                ffma2(acc[g][b], wv[g].x, hv.x);
                ffma2(acc[g][b], wv[g].y, hv.y);
            }
        }
    }
}

extern "C" __global__ void __launch_bounds__(THREADS, 1)
lstm_kernel(const float* __restrict__ x,
            const float* __restrict__ w_ih0, const float* __restrict__ w_hh0,
            const float* __restrict__ b_ih0, const float* __restrict__ b_hh0,
            const float* __restrict__ w_ih1, const float* __restrict__ w_hh1,
            const float* __restrict__ b_ih1, const float* __restrict__ b_hh1,
            const float* __restrict__ fc1_w, const float* __restrict__ fc1_b,
            const float* __restrict__ fc2_w, const float* __restrict__ fc2_b,
            float* __restrict__ out) {
    extern __shared__ float sm[];
    float* wsm = sm;                 // 3 matrices, padded rows
    float* xs  = sm + OFF_X;         // x transposed: [s][b_local], stride 33
    float* h1b = sm + OFF_H1;        // [32 b][32 k]
    float* h2b = sm + OFF_H2;

    const int tid  = threadIdx.x;
    const int bblk = blockIdx.x * BPB;

    // ---- init: weights into padded smem ----
    for (int i = tid; i < 3 * 128 * 32; i += THREADS) {
        int m = i >> 12;            // /4096
        int r = (i >> 5) & 127;
        int k = i & 31;
        const float* src = (m == 0) ? w_hh0 : (m == 1) ? w_ih1 : w_hh1;
        wsm[m * W_MAT + r * W_STRIDE + k] = src[r * 32 + k];
    }
    // ---- x tile, transposed to [s][b] (coalesced global reads) ----
    for (int i = tid; i < BPB * SEQ; i += THREADS) {
        int b = i >> 9;             // /512
        int s = i & (SEQ - 1);
        xs[s * X_STRIDE + b] = x[(size_t)(bblk + b) * SEQ + s];
    }
    // ---- h buffers zero ----
    for (int i = tid; i < BPB * HD; i += THREADS) { h1b[i] = 0.0f; h2b[i] = 0.0f; }
    __syncthreads();

    const int w  = tid >> 5;
    const int j  = tid & 31;
    const int b0 = w * NBW;

    const char* w0base = (const char*)wsm + (size_t)j * (W_STRIDE * 4);
    const char* w1base = (const char*)(wsm + W_MAT)     + (size_t)j * (W_STRIDE * 4);
    const char* w2base = (const char*)(wsm + 2 * W_MAT) + (size_t)j * (W_STRIDE * 4);
    const float* h1w = h1b + b0 * HD;
    const float* h2w = h2b + b0 * HD;

    float wx[4], bi0[4], bi1[4];
#pragma unroll
    for (int g = 0; g < 4; ++g) {
        int r = g * 32 + j;
        wx[g]  = w_ih0[r];
        bi0[g] = b_ih0[r] + b_hh0[r];
        bi1[g] = b_ih1[r] + b_hh1[r];
    }

    float c1[NBW], c2[NBW];
#pragma unroll
    for (int b = 0; b < NBW; ++b) { c1[b] = 0.0f; c2[b] = 0.0f; }

#pragma unroll 1
    for (int s = 0; s < SEQ; ++s) {
        // ================= Layer 1 =================
        u64 acc[4][NBW];
#pragma unroll
        for (int g = 0; g < 4; ++g)
#pragma unroll
            for (int b = 0; b < NBW; ++b) acc[g][b] = 0ull;

        matvec_acc(acc, w0base, h1w);
        __syncwarp();                      // all lanes done reading old h1

        float h1n[NBW];
#pragma unroll
        for (int b = 0; b < NBW; ++b) {
            float xv = xs[s * X_STRIDE + b0 + b];
            float2 t;
            t = unpk(acc[0][b]); float gi = sigm (t.x + t.y + fmaf(xv, wx[0], bi0[0]));
            t = unpk(acc[1][b]); float gf = sigm (t.x + t.y + fmaf(xv, wx[1], bi0[1]));
            t = unpk(acc[2][b]); float gg = tanhx(t.x + t.y + fmaf(xv, wx[2], bi0[2]));
            t = unpk(acc[3][b]); float go = sigm (t.x + t.y + fmaf(xv, wx[3], bi0[3]));
            float cn = fmaf(gf, c1[b], gi * gg);
            c1[b] = cn;
            h1n[b] = go * tanhx(cn);
        }
#pragma unroll
        for (int b = 0; b < NBW; ++b) h1b[(b0 + b) * HD + j] = h1n[b];
        __syncwarp();                      // new h1 visible

        // ================= Layer 2 =================
#pragma unroll
        for (int g = 0; g < 4; ++g)
#pragma unroll
            for (int b = 0; b < NBW; ++b) acc[g][b] = 0ull;

        matvec_acc(acc, w1base, h1w);      // input proj from new h1
        matvec_acc(acc, w2base, h2w);      // recurrent from old h2
        __syncwarp();                      // all lanes done reading h1/h2

        float h2n[NBW];
#pragma unroll
        for (int b = 0; b < NBW; ++b) {
            float2 t;
            t = unpk(acc[0][b]); float gi = sigm (t.x + t.y + bi1[0]);
            t = unpk(acc[1][b]); float gf = sigm (t.x + t.y + bi1[1]);
            t = unpk(acc[2][b]); float gg = tanhx(t.x + t.y + bi1[2]);
            t = unpk(acc[3][b]); float go = sigm (t.x + t.y + bi1[3]);
            float cn = fmaf(gf, c2[b], gi * gg);
            c2[b] = cn;
            h2n[b] = go * tanhx(cn);
        }
#pragma unroll
        for (int b = 0; b < NBW; ++b) h2b[(b0 + b) * HD + j] = h2n[b];
        __syncwarp();                      // new h2 visible
    }

    // ================= FC head (last h2) =================
    if (j < NBW) {
        const int bl = b0 + j;
        const float* h = h2b + bl * HD;
        float a1[16];
#pragma unroll
        for (int l = 0; l < 16; ++l) a1[l] = fc1_b[l];
#pragma unroll
        for (int k = 0; k < HD; ++k) {
            float hv = h[k];
#pragma unroll
            for (int l = 0; l < 16; ++l)
                a1[l] = fmaf(fc1_w[l * HD + k], hv, a1[l]);
        }
        float y = fc2_b[0];
#pragma unroll
        for (int l = 0; l < 16; ++l) {
            float a = a1[l];
            a = (a >= 0.0f) ? a : 0.2f * a;
            y = fmaf(fc2_w[l], a, y);
        }
        out[bblk + bl] = y;
    }
}

extern "C" void kernel_launch(void* const* d_in, const int* in_sizes, int n_in,
                              void* d_out, int out_size) {
    const float* x     = (const float*)d_in[0];
    const float* w_ih0 = (const float*)d_in[1];
    const float* w_hh0 = (const float*)d_in[2];
    const float* b_ih0 = (const float*)d_in[3];
    const float* b_hh0 = (const float*)d_in[4];
    const float* w_ih1 = (const float*)d_in[5];
    const float* w_hh1 = (const float*)d_in[6];
    const float* b_ih1 = (const float*)d_in[7];
    const float* b_hh1 = (const float*)d_in[8];
    const float* fc1_w = (const float*)d_in[9];
    const float* fc1_b = (const float*)d_in[10];
    const float* fc2_w = (const float*)d_in[11];
    const float* fc2_b = (const float*)d_in[12];
    float* out = (float*)d_out;

    int B = in_sizes[0] / SEQ;          // 4096
    int grid = B / BPB;                 // 128
    size_t smem = SMEM_FLOATS * sizeof(float);   // 131072

    cudaFuncSetAttribute(lstm_kernel, cudaFuncAttributeMaxDynamicSharedMemorySize, (int)smem);
    lstm_kernel<<<grid, THREADS, smem>>>(x, w_ih0, w_hh0, b_ih0, b_hh0,
                                         w_ih1, w_hh1, b_ih1, b_hh1,
                                         fc1_w, fc1_b, fc2_w, fc2_b, out);
}